// round 8
// baseline (speedup 1.0000x reference)
#include <cuda_runtime.h>
#include <cuda_fp16.h>
#include <cstdint>

#define NN     8192
#define F_IN   128
#define F_OUTD 64
#define L2E    1.4426950408889634f

#define ALPHA2_PK 0x32663266u   // half2(0.2, 0.2)
#define MESH2_PK  0xC5C5C5C5u   // half2(-5.7695, -5.7695)  (~ -4*log2(e); uniform
                                // offset, cancels exactly in softmax)

// ---------------------------------------------------------------------------
// Device scratch (allocations forbidden -> __device__ globals)
// ---------------------------------------------------------------------------
__device__ float    g_wh[NN * F_OUTD];
__device__ __half   g_whT16[F_OUTD * NN];    // [f][i] fp16 transpose of wh
__device__ float    g_src[NN];
__device__ float    g_dst[NN];
__device__ uint32_t g_dst16u[NN / 2];        // half2(dst[2u], dst[2u+1]) * L2E
__device__ float    g_part[256 * 128 * 66];  // [cta][row][64 num, 1 Z, pad]

// ---------------------------------------------------------------------------
// Kernel 1: WH = H @ W (fp32) + fp16 transpose WH^T. 32 rows per block.
// ---------------------------------------------------------------------------
__global__ __launch_bounds__(256) void wh_kernel(const float* __restrict__ h,
                                                 const float* __restrict__ w) {
    __shared__ __align__(16) float sW[F_IN * F_OUTD];  // 32 KB
    __shared__ __align__(16) float sH[32 * F_IN];      // 16 KB (reused as sT)
    int t = threadIdx.x;
    int i0 = blockIdx.x * 32;

    {
        float4* dw = (float4*)sW;
        const float4* swg = (const float4*)w;
        #pragma unroll
        for (int k = 0; k < 8; k++) dw[t + k * 256] = swg[t + k * 256];
        float4* dh = (float4*)sH;
        const float4* shg = (const float4*)(h + (size_t)i0 * F_IN);
        #pragma unroll
        for (int k = 0; k < 4; k++) dh[t + k * 256] = shg[t + k * 256];
    }
    __syncthreads();

    int f = t & 63;
    int rg = t >> 6;
    float acc[8] = {0.f, 0.f, 0.f, 0.f, 0.f, 0.f, 0.f, 0.f};
    #pragma unroll 4
    for (int k = 0; k < F_IN; k += 4) {
        float w0 = sW[(k + 0) * F_OUTD + f];
        float w1 = sW[(k + 1) * F_OUTD + f];
        float w2 = sW[(k + 2) * F_OUTD + f];
        float w3 = sW[(k + 3) * F_OUTD + f];
        #pragma unroll
        for (int m = 0; m < 8; m++) {
            float4 h4 = *(const float4*)&sH[(rg * 8 + m) * F_IN + k];
            acc[m] = fmaf(h4.x, w0, acc[m]);
            acc[m] = fmaf(h4.y, w1, acc[m]);
            acc[m] = fmaf(h4.z, w2, acc[m]);
            acc[m] = fmaf(h4.w, w3, acc[m]);
        }
    }
    #pragma unroll
    for (int m = 0; m < 8; m++)
        g_wh[(size_t)(i0 + rg * 8 + m) * F_OUTD + f] = acc[m];

    __syncthreads();
    __half* sT = (__half*)sH;   // [64 f][32 r]
    #pragma unroll
    for (int m = 0; m < 8; m++)
        sT[f * 32 + rg * 8 + m] = __float2half_rn(acc[m]);
    __syncthreads();
    {
        int f2 = t >> 2, seg = t & 3;
        uint4 v = *(const uint4*)(sT + f2 * 32 + seg * 8);
        *(uint4*)(g_whT16 + (size_t)f2 * NN + i0 + seg * 8) = v;
    }
}

// ---------------------------------------------------------------------------
// Kernel 2: src / dst vectors
// ---------------------------------------------------------------------------
__global__ __launch_bounds__(256) void srcdst_kernel(const float* __restrict__ edge,
                                                     const float* __restrict__ att,
                                                     const float* __restrict__ w_edge) {
    int warp = threadIdx.x >> 5;
    int lane = threadIdx.x & 31;
    int i = blockIdx.x * 8 + warp;
    const float* whr = g_wh + (size_t)i * F_OUTD;

    float wl = whr[lane], wh2 = whr[lane + 32];
    float s = wl * att[lane]      + wh2 * att[lane + 32];
    float d = wl * att[64 + lane] + wh2 * att[96 + lane];
    float c = w_edge[lane] * att[128 + lane] + w_edge[lane + 32] * att[160 + lane];
    #pragma unroll
    for (int o = 16; o; o >>= 1) {
        s += __shfl_xor_sync(0xffffffffu, s, o);
        d += __shfl_xor_sync(0xffffffffu, d, o);
        c += __shfl_xor_sync(0xffffffffu, c, o);
    }
    if (lane == 0) {
        g_src[i] = s + edge[i] * c;
        g_dst[i] = d;
    }
}

// pack dst*L2E into half2 (even col in .lo)
__global__ __launch_bounds__(256) void packdst_kernel() {
    int u = blockIdx.x * 256 + threadIdx.x;   // 0..4095
    float2 d = *(const float2*)(g_dst + 2 * u);
    __half2 p = __floats2half2_rn(d.x * L2E, d.y * L2E);
    g_dst16u[u] = *(const uint32_t*)&p;
}

// ---------------------------------------------------------------------------
// mma.sync / ldmatrix helpers
// ---------------------------------------------------------------------------
__device__ __forceinline__ uint32_t smem_u32(const void* p) {
    uint32_t a;
    asm("{ .reg .u64 t; cvta.to.shared.u64 t, %1; cvt.u32.u64 %0, t; }"
        : "=r"(a) : "l"(p));
    return a;
}
__device__ __forceinline__ void mma16816(float* c, uint32_t a0, uint32_t a1,
                                         uint32_t a2, uint32_t a3,
                                         uint32_t b0, uint32_t b1) {
    asm volatile(
        "mma.sync.aligned.m16n8k16.row.col.f32.f16.f16.f32 "
        "{%0,%1,%2,%3}, {%4,%5,%6,%7}, {%8,%9}, {%0,%1,%2,%3};"
        : "+f"(c[0]), "+f"(c[1]), "+f"(c[2]), "+f"(c[3])
        : "r"(a0), "r"(a1), "r"(a2), "r"(a3), "r"(b0), "r"(b1));
}
__device__ __forceinline__ void ldsm_x4(uint32_t* r, uint32_t addr) {
    asm volatile("ldmatrix.sync.aligned.m8n8.x4.shared.b16 {%0,%1,%2,%3}, [%4];"
                 : "=r"(r[0]), "=r"(r[1]), "=r"(r[2]), "=r"(r[3]) : "r"(addr));
}
// packed fp16 attention pair: src2/d2 are already *L2E; mask by multiply.
// w = 2^( leaky(L2E*(src+dst)) - 4*L2E ) * mask
__device__ __forceinline__ uint32_t wpair16(uint32_t src2, uint32_t d2, int2 a) {
    uint32_t e, m, l, g, w;
    asm("add.f16x2 %0, %1, %2;"    : "=r"(e) : "r"(src2), "r"(d2));
    asm("mul.f16x2 %0, %1, %2;"    : "=r"(m) : "r"(e), "r"(ALPHA2_PK));
    asm("max.f16x2 %0, %1, %2;"    : "=r"(l) : "r"(e), "r"(m));
    asm("add.f16x2 %0, %1, %2;"    : "=r"(g) : "r"(l), "r"(MESH2_PK));
    asm("ex2.approx.f16x2 %0, %0;" : "+r"(g));
    uint32_t msk = (uint32_t)a.x * 0x3C00u + (uint32_t)a.y * 0x3C000000u;
    asm("mul.f16x2 %0, %1, %2;"    : "=r"(w) : "r"(g), "r"(msk));
    return w;
}

// ---------------------------------------------------------------------------
// Kernel 3: HMMA masked-softmax aggregation.
// Grid 256 = 64 row-blocks x 4 j-quarters; 2 CTAs/SM. Flattened 128-k-step
// stream with 2-step adjacency lookahead (no per-tile pipeline drain).
// ---------------------------------------------------------------------------
__global__ void __launch_bounds__(256, 2) attn_kernel(const int* __restrict__ adj) {
    __shared__ __align__(1024) __half sB[2][64 * 128];   // 2 x 16 KB

    int t = threadIdx.x, lane = t & 31, w = t >> 5;
    int bx = blockIdx.x;
    int i0 = (bx >> 2) * 128, j0 = (bx & 3) * 2048;

    int l4 = lane & 3;
    int lr = lane >> 2;
    int row0 = w * 16 + lr;

    float acc[8][4];
    float zc[4];
    #pragma unroll
    for (int p = 0; p < 8; p++)
        #pragma unroll
        for (int q = 0; q < 4; q++) acc[p][q] = 0.f;
    #pragma unroll
    for (int q = 0; q < 4; q++) zc[q] = 0.f;

    // src * L2E, replicated half2
    __half2 s0h = __float2half2_rn(g_src[i0 + row0] * L2E);
    __half2 s1h = __float2half2_rn(g_src[i0 + row0 + 8] * L2E);
    uint32_t srcL0 = *(const uint32_t*)&s0h;
    uint32_t srcL1 = *(const uint32_t*)&s1h;

    const int* ap = adj + (size_t)(i0 + row0) * NN + j0 + l4 * 2;
    const uint32_t* dpp = g_dst16u + (j0 >> 1) + l4;

    // B-copy indices
    int fB = t >> 2, qb = (t & 3) * 4;
    const uint4* bsrc_base = (const uint4*)(g_whT16 + (size_t)fB * NN + j0);
    // ldmatrix per-lane geometry
    int fo  = (lane & 7) + ((lane & 16) >> 1);
    int cb  = (lane >> 3) & 1;
    int sw7 = lane & 7;
    uint32_t sb_base = smem_u32(sB);

    // prologue: fill B buffer 0
    #pragma unroll
    for (int q = 0; q < 4; q++) {
        uint4 v = bsrc_base[qb + q];
        *(uint4*)((char*)(sB[0] + fB * 128) + (((qb + q) ^ (fB & 7)) << 4)) = v;
    }

    // prologue: adjacency/dst 2-stage ring (g = 0, 1)
    int2 sA[2][4];
    uint32_t sD[2][2];
    #pragma unroll
    for (int st = 0; st < 2; st++) {
        sA[st][0] = *(const int2*)(ap + st * 16);
        sA[st][1] = *(const int2*)(ap + st * 16 + 8);
        sA[st][2] = *(const int2*)(ap + st * 16 + 8 * NN);
        sA[st][3] = *(const int2*)(ap + st * 16 + 8 * NN + 8);
        sD[st][0] = dpp[st * 8];
        sD[st][1] = dpp[st * 8 + 4];
    }

    const uint32_t ONES = 0x3C003C00u;  // fp16 {1,1}

    for (int g = 0; g < 128; g++) {
        int ks = g & 7, lt = g >> 3, s = lt & 1, st = g & 1;

        if (ks == 0) {
            __syncthreads();
            if (lt < 15) {   // prefetch next B tile into the other buffer
                const uint4* bs =
                    (const uint4*)((const __half*)bsrc_base + (lt + 1) * 128);
                #pragma unroll
                for (int q = 0; q < 4; q++) {
                    uint4 v = bs[qb + q];
                    *(uint4*)((char*)(sB[s ^ 1] + fB * 128) +
                              (((qb + q) ^ (fB & 7)) << 4)) = v;
                }
            }
        }

        // consume stage st, then refill it for g+2
        int2 c00 = sA[st][0], c01 = sA[st][1], c10 = sA[st][2], c11 = sA[st][3];
        uint32_t dd0 = sD[st][0], dd1 = sD[st][1];
        if (g < 126) {
            sA[st][0] = *(const int2*)(ap + (g + 2) * 16);
            sA[st][1] = *(const int2*)(ap + (g + 2) * 16 + 8);
            sA[st][2] = *(const int2*)(ap + (g + 2) * 16 + 8 * NN);
            sA[st][3] = *(const int2*)(ap + (g + 2) * 16 + 8 * NN + 8);
            sD[st][0] = dpp[(g + 2) * 8];
            sD[st][1] = dpp[(g + 2) * 8 + 4];
        }

        uint32_t fa0 = wpair16(srcL0, dd0, c00);   // rows 0-7,  k low
        uint32_t fa1 = wpair16(srcL1, dd0, c10);   // rows 8-15, k low
        uint32_t fa2 = wpair16(srcL0, dd1, c01);   // rows 0-7,  k+8
        uint32_t fa3 = wpair16(srcL1, dd1, c11);   // rows 8-15, k+8

        uint32_t lmbase = sb_base + (uint32_t)s * 16384u + (uint32_t)fo * 256u;
        uint32_t chx = (uint32_t)(((2 * ks + cb) ^ sw7) << 4);
        uint32_t b[16];
        #pragma unroll
        for (int pp = 0; pp < 4; pp++)
            ldsm_x4(b + pp * 4, lmbase + (uint32_t)(pp * 4096) + chx);

        #pragma unroll
        for (int p = 0; p < 8; p++)
            mma16816(acc[p], fa0, fa1, fa2, fa3, b[p * 2], b[p * 2 + 1]);
        mma16816(zc, fa0, fa1, fa2, fa3, ONES, ONES);
    }

    // epilogue: C frags -> g_part (stride 66, aligned float2)
    size_t rbase = (size_t)bx * 128 + row0;
    #pragma unroll
    for (int p = 0; p < 8; p++) {
        float* o0 = g_part + rbase * 66 + p * 8 + l4 * 2;
        float* o1 = o0 + 8 * 66;
        *(float2*)o0 = make_float2(acc[p][0], acc[p][1]);
        *(float2*)o1 = make_float2(acc[p][2], acc[p][3]);
    }
    if (l4 == 0) {
        g_part[rbase * 66 + 64] = zc[0];
        g_part[(rbase + 8) * 66 + 64] = zc[2];
    }
}

// ---------------------------------------------------------------------------
// Kernel 4: combine 4 j-quarter partials, normalize, ELU (float2 vectorized)
// ---------------------------------------------------------------------------
__global__ __launch_bounds__(256) void combine_kernel(float* __restrict__ out) {
    int u = blockIdx.x * 256 + threadIdx.x;   // 0 .. 262143 (float2 units)
    int i = u >> 5, fp = u & 31;
    int b0 = (i >> 7) * 4, r = i & 127;
    const float* p = g_part + (size_t)(b0 * 128 + r) * 66;
    float nx = 0.f, ny = 0.f, z = 0.f;
    #pragma unroll
    for (int q = 0; q < 4; q++) {
        float2 v = *(const float2*)(p + (size_t)q * 128 * 66 + fp * 2);
        nx += v.x; ny += v.y;
        z += p[(size_t)q * 128 * 66 + 64];
    }
    float vx = nx / z, vy = ny / z;
    vx = (vx > 0.f) ? vx : expm1f(vx);
    vy = (vy > 0.f) ? vy : expm1f(vy);
    *(float2*)(out + (size_t)i * F_OUTD + fp * 2) = make_float2(vx, vy);
}

// ---------------------------------------------------------------------------
// Launch. Inputs: 0 h_nodes(8192x128 f32), 1 edge(8192 f32), 2 adj(8192^2 i32),
//                 3 weight(128x64 f32), 4 att(192 f32), 5 w_edge(64 f32)
// ---------------------------------------------------------------------------
extern "C" void kernel_launch(void* const* d_in, const int* in_sizes, int n_in,
                              void* d_out, int out_size) {
    const float* h      = (const float*)d_in[0];
    const float* edge   = (const float*)d_in[1];
    const int*   adj    = (const int*)d_in[2];
    const float* weight = (const float*)d_in[3];
    const float* att    = (const float*)d_in[4];
    const float* w_edge = (const float*)d_in[5];
    float* out = (float*)d_out;

    wh_kernel<<<NN / 32, 256>>>(h, weight);
    srcdst_kernel<<<NN / 8, 256>>>(edge, att, w_edge);
    packdst_kernel<<<NN / 512, 256>>>();
    attn_kernel<<<256, 256>>>(adj);
    combine_kernel<<<NN * F_OUTD / 512, 256>>>(out);
}

// round 9
// speedup vs baseline: 1.4845x; 1.4845x over previous
#include <cuda_runtime.h>
#include <cuda_fp16.h>
#include <cstdint>

#define NN     8192
#define F_IN   128
#define F_OUTD 64
#define L2E    1.4426950408889634f

#define ALPHA2_PK 0x32663266u   // half2(0.2, 0.2)
#define MESH2_PK  0xC5C5C5C5u   // half2(-5.7695, -5.7695) (~ -4*log2(e); uniform
                                // offset, cancels exactly in softmax)

// ---------------------------------------------------------------------------
// Device scratch (allocations forbidden -> __device__ globals)
// ---------------------------------------------------------------------------
__device__ float    g_wh[NN * F_OUTD];
__device__ __half   g_whT16[F_OUTD * NN];    // [f][i] fp16 transpose of wh
__device__ float    g_src[NN];
__device__ float    g_dst[NN];
__device__ uint32_t g_dst16u[NN / 2];        // half2(dst[2u], dst[2u+1]) * L2E
__device__ float    g_part[256 * 128 * 66];  // [cta][row][64 num, 1 Z, pad]

// ---------------------------------------------------------------------------
// Kernel 1: WH = H @ W (fp32) + fp16 transpose WH^T. 32 rows per block.
// ---------------------------------------------------------------------------
__global__ __launch_bounds__(256) void wh_kernel(const float* __restrict__ h,
                                                 const float* __restrict__ w) {
    __shared__ __align__(16) float sW[F_IN * F_OUTD];  // 32 KB
    __shared__ __align__(16) float sH[32 * F_IN];      // 16 KB (reused as sT)
    int t = threadIdx.x;
    int i0 = blockIdx.x * 32;

    {
        float4* dw = (float4*)sW;
        const float4* swg = (const float4*)w;
        #pragma unroll
        for (int k = 0; k < 8; k++) dw[t + k * 256] = swg[t + k * 256];
        float4* dh = (float4*)sH;
        const float4* shg = (const float4*)(h + (size_t)i0 * F_IN);
        #pragma unroll
        for (int k = 0; k < 4; k++) dh[t + k * 256] = shg[t + k * 256];
    }
    __syncthreads();

    int f = t & 63;
    int rg = t >> 6;
    float acc[8] = {0.f, 0.f, 0.f, 0.f, 0.f, 0.f, 0.f, 0.f};
    #pragma unroll 4
    for (int k = 0; k < F_IN; k += 4) {
        float w0 = sW[(k + 0) * F_OUTD + f];
        float w1 = sW[(k + 1) * F_OUTD + f];
        float w2 = sW[(k + 2) * F_OUTD + f];
        float w3 = sW[(k + 3) * F_OUTD + f];
        #pragma unroll
        for (int m = 0; m < 8; m++) {
            float4 h4 = *(const float4*)&sH[(rg * 8 + m) * F_IN + k];
            acc[m] = fmaf(h4.x, w0, acc[m]);
            acc[m] = fmaf(h4.y, w1, acc[m]);
            acc[m] = fmaf(h4.z, w2, acc[m]);
            acc[m] = fmaf(h4.w, w3, acc[m]);
        }
    }
    #pragma unroll
    for (int m = 0; m < 8; m++)
        g_wh[(size_t)(i0 + rg * 8 + m) * F_OUTD + f] = acc[m];

    __syncthreads();
    __half* sT = (__half*)sH;   // [64 f][32 r]
    #pragma unroll
    for (int m = 0; m < 8; m++)
        sT[f * 32 + rg * 8 + m] = __float2half_rn(acc[m]);
    __syncthreads();
    {
        int f2 = t >> 2, seg = t & 3;
        uint4 v = *(const uint4*)(sT + f2 * 32 + seg * 8);
        *(uint4*)(g_whT16 + (size_t)f2 * NN + i0 + seg * 8) = v;
    }
}

// ---------------------------------------------------------------------------
// Kernel 2: src / dst vectors
// ---------------------------------------------------------------------------
__global__ __launch_bounds__(256) void srcdst_kernel(const float* __restrict__ edge,
                                                     const float* __restrict__ att,
                                                     const float* __restrict__ w_edge) {
    int warp = threadIdx.x >> 5;
    int lane = threadIdx.x & 31;
    int i = blockIdx.x * 8 + warp;
    const float* whr = g_wh + (size_t)i * F_OUTD;

    float wl = whr[lane], wh2 = whr[lane + 32];
    float s = wl * att[lane]      + wh2 * att[lane + 32];
    float d = wl * att[64 + lane] + wh2 * att[96 + lane];
    float c = w_edge[lane] * att[128 + lane] + w_edge[lane + 32] * att[160 + lane];
    #pragma unroll
    for (int o = 16; o; o >>= 1) {
        s += __shfl_xor_sync(0xffffffffu, s, o);
        d += __shfl_xor_sync(0xffffffffu, d, o);
        c += __shfl_xor_sync(0xffffffffu, c, o);
    }
    if (lane == 0) {
        g_src[i] = s + edge[i] * c;
        g_dst[i] = d;
    }
}

// pack dst*L2E into half2 (even col in .lo)
__global__ __launch_bounds__(256) void packdst_kernel() {
    int u = blockIdx.x * 256 + threadIdx.x;   // 0..4095
    float2 d = *(const float2*)(g_dst + 2 * u);
    __half2 p = __floats2half2_rn(d.x * L2E, d.y * L2E);
    g_dst16u[u] = *(const uint32_t*)&p;
}

// ---------------------------------------------------------------------------
// mma.sync / ldmatrix helpers
// ---------------------------------------------------------------------------
__device__ __forceinline__ uint32_t smem_u32(const void* p) {
    uint32_t a;
    asm("{ .reg .u64 t; cvta.to.shared.u64 t, %1; cvt.u32.u64 %0, t; }"
        : "=r"(a) : "l"(p));
    return a;
}
__device__ __forceinline__ void mma16816(float* c, uint32_t a0, uint32_t a1,
                                         uint32_t a2, uint32_t a3,
                                         uint32_t b0, uint32_t b1) {
    asm volatile(
        "mma.sync.aligned.m16n8k16.row.col.f32.f16.f16.f32 "
        "{%0,%1,%2,%3}, {%4,%5,%6,%7}, {%8,%9}, {%0,%1,%2,%3};"
        : "+f"(c[0]), "+f"(c[1]), "+f"(c[2]), "+f"(c[3])
        : "r"(a0), "r"(a1), "r"(a2), "r"(a3), "r"(b0), "r"(b1));
}
__device__ __forceinline__ void ldsm_x4(uint32_t* r, uint32_t addr) {
    asm volatile("ldmatrix.sync.aligned.m8n8.x4.shared.b16 {%0,%1,%2,%3}, [%4];"
                 : "=r"(r[0]), "=r"(r[1]), "=r"(r[2]), "=r"(r[3]) : "r"(addr));
}
// streaming adjacency load (no reuse -> evict-first)
__device__ __forceinline__ int2 ldcs2(const int* p) {
    int2 v;
    asm volatile("ld.global.cs.v2.s32 {%0, %1}, [%2];"
                 : "=r"(v.x), "=r"(v.y) : "l"(p));
    return v;
}
// packed fp16 attention pair: src2/d2 are already *L2E; mask by multiply.
// w = 2^( leaky(L2E*(src+dst)) - 4*L2E ) * mask
__device__ __forceinline__ uint32_t wpair16(uint32_t src2, uint32_t d2, int2 a) {
    uint32_t e, m, l, g, w;
    asm("add.f16x2 %0, %1, %2;"    : "=r"(e) : "r"(src2), "r"(d2));
    asm("mul.f16x2 %0, %1, %2;"    : "=r"(m) : "r"(e), "r"(ALPHA2_PK));
    asm("max.f16x2 %0, %1, %2;"    : "=r"(l) : "r"(e), "r"(m));
    asm("add.f16x2 %0, %1, %2;"    : "=r"(g) : "r"(l), "r"(MESH2_PK));
    asm("ex2.approx.f16x2 %0, %0;" : "+r"(g));
    uint32_t msk = (uint32_t)a.x * 0x3C00u + (uint32_t)a.y * 0x3C000000u;
    asm("mul.f16x2 %0, %1, %2;"    : "=r"(w) : "r"(g), "r"(msk));
    return w;
}

// ---------------------------------------------------------------------------
// Kernel 3: HMMA masked-softmax aggregation.
// Grid 256 = 64 row-blocks x 4 j-quarters; 2 CTAs/SM. Nested tile loop with
// FULLY UNROLLED k-steps so the software-pipeline rings use compile-time
// indices (round-8 lesson: runtime-indexed rings spill to local).
// adj ring depth 4 (~900+ cyc lookahead > 577 DRAM), dst ring depth 2 (L2).
// ---------------------------------------------------------------------------
__global__ void __launch_bounds__(256, 2) attn_kernel(const int* __restrict__ adj) {
    __shared__ __align__(1024) __half sB[2][64 * 128];   // 2 x 16 KB

    int t = threadIdx.x, lane = t & 31, w = t >> 5;
    int bx = blockIdx.x;
    int i0 = (bx >> 2) * 128, j0 = (bx & 3) * 2048;

    int l4 = lane & 3;
    int lr = lane >> 2;
    int row0 = w * 16 + lr;

    float acc[8][4];
    float zc[4];
    #pragma unroll
    for (int p = 0; p < 8; p++)
        #pragma unroll
        for (int q = 0; q < 4; q++) acc[p][q] = 0.f;
    #pragma unroll
    for (int q = 0; q < 4; q++) zc[q] = 0.f;

    // src * L2E, replicated half2
    __half2 s0h = __float2half2_rn(g_src[i0 + row0] * L2E);
    __half2 s1h = __float2half2_rn(g_src[i0 + row0 + 8] * L2E);
    uint32_t srcL0 = *(const uint32_t*)&s0h;
    uint32_t srcL1 = *(const uint32_t*)&s1h;

    const int* ap = adj + (size_t)(i0 + row0) * NN + j0 + l4 * 2;
    const uint32_t* dpp = g_dst16u + (j0 >> 1) + l4;

    // B-copy indices
    int fB = t >> 2, qb = (t & 3) * 4;
    const uint4* bsrc_base = (const uint4*)(g_whT16 + (size_t)fB * NN + j0);
    // ldmatrix per-lane geometry
    int fo  = (lane & 7) + ((lane & 16) >> 1);
    int cb  = (lane >> 3) & 1;
    int sw7 = lane & 7;
    uint32_t sb_base = smem_u32(sB);

    // prologue: fill B buffer 0
    #pragma unroll
    for (int q = 0; q < 4; q++) {
        uint4 v = bsrc_base[qb + q];
        *(uint4*)((char*)(sB[0] + fB * 128) + (((qb + q) ^ (fB & 7)) << 4)) = v;
    }

    // prologue: rings. adj: steps 0..3; dst: steps 0..1. All indices literal.
    int2 rA[4][4];
    uint32_t rD[2][2];
    #pragma unroll
    for (int st = 0; st < 4; st++) {
        rA[st][0] = ldcs2(ap + st * 16);
        rA[st][1] = ldcs2(ap + st * 16 + 8);
        rA[st][2] = ldcs2(ap + st * 16 + 8 * NN);
        rA[st][3] = ldcs2(ap + st * 16 + 8 * NN + 8);
    }
    #pragma unroll
    for (int st = 0; st < 2; st++) {
        rD[st][0] = dpp[st * 8];
        rD[st][1] = dpp[st * 8 + 4];
    }

    const uint32_t ONES = 0x3C003C00u;  // fp16 {1,1}

    for (int lt = 0; lt < 16; lt++) {
        int s = lt & 1;
        __syncthreads();
        if (lt < 15) {   // prefetch next B tile into the other buffer
            const uint4* bs = (const uint4*)((const __half*)bsrc_base + (lt + 1) * 128);
            #pragma unroll
            for (int q = 0; q < 4; q++) {
                uint4 v = bs[qb + q];
                *(uint4*)((char*)(sB[s ^ 1] + fB * 128) +
                          (((qb + q) ^ (fB & 7)) << 4)) = v;
            }
        }

        uint32_t lmbase = sb_base + (uint32_t)s * 16384u + (uint32_t)fo * 256u;
        int gbase = lt * 8;

        #pragma unroll
        for (int ks = 0; ks < 8; ks++) {          // ks is a literal (unrolled)
            const int sa = ks & 3, sd = ks & 1;   // compile-time ring slots
            int2 c00 = rA[sa][0], c01 = rA[sa][1];
            int2 c10 = rA[sa][2], c11 = rA[sa][3];
            uint32_t dd0 = rD[sd][0], dd1 = rD[sd][1];

            // refill slot sa with step g+4, slot sd with step g+2
            if (lt < 15 || ks < 4) {
                const int* an = ap + (gbase + ks + 4) * 16;
                rA[sa][0] = ldcs2(an);
                rA[sa][1] = ldcs2(an + 8);
                rA[sa][2] = ldcs2(an + 8 * NN);
                rA[sa][3] = ldcs2(an + 8 * NN + 8);
            }
            if (lt < 15 || ks < 6) {
                rD[sd][0] = dpp[(gbase + ks + 2) * 8];
                rD[sd][1] = dpp[(gbase + ks + 2) * 8 + 4];
            }

            uint32_t fa0 = wpair16(srcL0, dd0, c00);   // rows 0-7,  k low
            uint32_t fa1 = wpair16(srcL1, dd0, c10);   // rows 8-15, k low
            uint32_t fa2 = wpair16(srcL0, dd1, c01);   // rows 0-7,  k+8
            uint32_t fa3 = wpair16(srcL1, dd1, c11);   // rows 8-15, k+8

            uint32_t chx = (uint32_t)(((2 * ks + cb) ^ sw7) << 4);
            uint32_t b[16];
            #pragma unroll
            for (int pp = 0; pp < 4; pp++)
                ldsm_x4(b + pp * 4, lmbase + (uint32_t)(pp * 4096) + chx);

            #pragma unroll
            for (int p = 0; p < 8; p++)
                mma16816(acc[p], fa0, fa1, fa2, fa3, b[p * 2], b[p * 2 + 1]);
            mma16816(zc, fa0, fa1, fa2, fa3, ONES, ONES);
        }
    }

    // epilogue: C frags -> g_part (stride 66, aligned float2)
    size_t rbase = (size_t)bx * 128 + row0;
    #pragma unroll
    for (int p = 0; p < 8; p++) {
        float* o0 = g_part + rbase * 66 + p * 8 + l4 * 2;
        float* o1 = o0 + 8 * 66;
        *(float2*)o0 = make_float2(acc[p][0], acc[p][1]);
        *(float2*)o1 = make_float2(acc[p][2], acc[p][3]);
    }
    if (l4 == 0) {
        g_part[rbase * 66 + 64] = zc[0];
        g_part[(rbase + 8) * 66 + 64] = zc[2];
    }
}

// ---------------------------------------------------------------------------
// Kernel 4: combine 4 j-quarter partials, normalize, ELU (float2 vectorized)
// ---------------------------------------------------------------------------
__global__ __launch_bounds__(256) void combine_kernel(float* __restrict__ out) {
    int u = blockIdx.x * 256 + threadIdx.x;   // 0 .. 262143 (float2 units)
    int i = u >> 5, fp = u & 31;
    int b0 = (i >> 7) * 4, r = i & 127;
    const float* p = g_part + (size_t)(b0 * 128 + r) * 66;
    float nx = 0.f, ny = 0.f, z = 0.f;
    #pragma unroll
    for (int q = 0; q < 4; q++) {
        float2 v = *(const float2*)(p + (size_t)q * 128 * 66 + fp * 2);
        nx += v.x; ny += v.y;
        z += p[(size_t)q * 128 * 66 + 64];
    }
    float vx = nx / z, vy = ny / z;
    vx = (vx > 0.f) ? vx : expm1f(vx);
    vy = (vy > 0.f) ? vy : expm1f(vy);
    *(float2*)(out + (size_t)i * F_OUTD + fp * 2) = make_float2(vx, vy);
}

// ---------------------------------------------------------------------------
// Launch. Inputs: 0 h_nodes(8192x128 f32), 1 edge(8192 f32), 2 adj(8192^2 i32),
//                 3 weight(128x64 f32), 4 att(192 f32), 5 w_edge(64 f32)
// ---------------------------------------------------------------------------
extern "C" void kernel_launch(void* const* d_in, const int* in_sizes, int n_in,
                              void* d_out, int out_size) {
    const float* h      = (const float*)d_in[0];
    const float* edge   = (const float*)d_in[1];
    const int*   adj    = (const int*)d_in[2];
    const float* weight = (const float*)d_in[3];
    const float* att    = (const float*)d_in[4];
    const float* w_edge = (const float*)d_in[5];
    float* out = (float*)d_out;

    wh_kernel<<<NN / 32, 256>>>(h, weight);
    srcdst_kernel<<<NN / 8, 256>>>(edge, att, w_edge);
    packdst_kernel<<<NN / 512, 256>>>();
    attn_kernel<<<256, 256>>>(adj);
    combine_kernel<<<NN * F_OUTD / 512, 256>>>(out);
}

// round 10
// speedup vs baseline: 1.7461x; 1.1762x over previous
#include <cuda_runtime.h>
#include <cuda_fp16.h>
#include <cstdint>

#define NN     8192
#define F_IN   128
#define F_OUTD 64
#define L2E    1.4426950408889634f

#define ALPHA2_PK 0x32663266u   // half2(0.2, 0.2)
#define MESH2_PK  0xC5C5C5C5u   // half2(-5.7695, -5.7695) (~ -4*log2(e); uniform
                                // offset, cancels exactly in softmax)

// ---------------------------------------------------------------------------
// Device scratch (allocations forbidden -> __device__ globals)
// ---------------------------------------------------------------------------
__device__ float    g_wh[NN * F_OUTD];
__device__ __half   g_whT16[F_OUTD * NN];    // [f][i] fp16 transpose of wh
__device__ float    g_src[NN];
__device__ float    g_dst[NN];
__device__ uint32_t g_dst16u[NN / 2];        // half2(dst[2u], dst[2u+1]) * L2E
__device__ float    g_part[256 * 128 * 66];  // [cta][row][64 num, 1 Z, pad]

// ---------------------------------------------------------------------------
// Kernel 1: WH = H @ W (fp32) + fp16 transpose WH^T. 32 rows per block.
// ---------------------------------------------------------------------------
__global__ __launch_bounds__(256) void wh_kernel(const float* __restrict__ h,
                                                 const float* __restrict__ w) {
    __shared__ __align__(16) float sW[F_IN * F_OUTD];  // 32 KB
    __shared__ __align__(16) float sH[32 * F_IN];      // 16 KB (reused as sT)
    int t = threadIdx.x;
    int i0 = blockIdx.x * 32;

    {
        float4* dw = (float4*)sW;
        const float4* swg = (const float4*)w;
        #pragma unroll
        for (int k = 0; k < 8; k++) dw[t + k * 256] = swg[t + k * 256];
        float4* dh = (float4*)sH;
        const float4* shg = (const float4*)(h + (size_t)i0 * F_IN);
        #pragma unroll
        for (int k = 0; k < 4; k++) dh[t + k * 256] = shg[t + k * 256];
    }
    __syncthreads();

    int f = t & 63;
    int rg = t >> 6;
    float acc[8] = {0.f, 0.f, 0.f, 0.f, 0.f, 0.f, 0.f, 0.f};
    #pragma unroll 4
    for (int k = 0; k < F_IN; k += 4) {
        float w0 = sW[(k + 0) * F_OUTD + f];
        float w1 = sW[(k + 1) * F_OUTD + f];
        float w2 = sW[(k + 2) * F_OUTD + f];
        float w3 = sW[(k + 3) * F_OUTD + f];
        #pragma unroll
        for (int m = 0; m < 8; m++) {
            float4 h4 = *(const float4*)&sH[(rg * 8 + m) * F_IN + k];
            acc[m] = fmaf(h4.x, w0, acc[m]);
            acc[m] = fmaf(h4.y, w1, acc[m]);
            acc[m] = fmaf(h4.z, w2, acc[m]);
            acc[m] = fmaf(h4.w, w3, acc[m]);
        }
    }
    #pragma unroll
    for (int m = 0; m < 8; m++)
        g_wh[(size_t)(i0 + rg * 8 + m) * F_OUTD + f] = acc[m];

    __syncthreads();
    __half* sT = (__half*)sH;   // [64 f][32 r]
    #pragma unroll
    for (int m = 0; m < 8; m++)
        sT[f * 32 + rg * 8 + m] = __float2half_rn(acc[m]);
    __syncthreads();
    {
        int f2 = t >> 2, seg = t & 3;
        uint4 v = *(const uint4*)(sT + f2 * 32 + seg * 8);
        *(uint4*)(g_whT16 + (size_t)f2 * NN + i0 + seg * 8) = v;
    }
}

// ---------------------------------------------------------------------------
// Kernel 2: src / dst vectors
// ---------------------------------------------------------------------------
__global__ __launch_bounds__(256) void srcdst_kernel(const float* __restrict__ edge,
                                                     const float* __restrict__ att,
                                                     const float* __restrict__ w_edge) {
    int warp = threadIdx.x >> 5;
    int lane = threadIdx.x & 31;
    int i = blockIdx.x * 8 + warp;
    const float* whr = g_wh + (size_t)i * F_OUTD;

    float wl = whr[lane], wh2 = whr[lane + 32];
    float s = wl * att[lane]      + wh2 * att[lane + 32];
    float d = wl * att[64 + lane] + wh2 * att[96 + lane];
    float c = w_edge[lane] * att[128 + lane] + w_edge[lane + 32] * att[160 + lane];
    #pragma unroll
    for (int o = 16; o; o >>= 1) {
        s += __shfl_xor_sync(0xffffffffu, s, o);
        d += __shfl_xor_sync(0xffffffffu, d, o);
        c += __shfl_xor_sync(0xffffffffu, c, o);
    }
    if (lane == 0) {
        g_src[i] = s + edge[i] * c;
        g_dst[i] = d;
    }
}

// pack dst*L2E into half2 (even col in .lo)
__global__ __launch_bounds__(256) void packdst_kernel() {
    int u = blockIdx.x * 256 + threadIdx.x;   // 0..4095
    float2 d = *(const float2*)(g_dst + 2 * u);
    __half2 p = __floats2half2_rn(d.x * L2E, d.y * L2E);
    g_dst16u[u] = *(const uint32_t*)&p;
}

// ---------------------------------------------------------------------------
// mma.sync / ldmatrix helpers
// ---------------------------------------------------------------------------
__device__ __forceinline__ uint32_t smem_u32(const void* p) {
    uint32_t a;
    asm("{ .reg .u64 t; cvta.to.shared.u64 t, %1; cvt.u32.u64 %0, t; }"
        : "=r"(a) : "l"(p));
    return a;
}
__device__ __forceinline__ void mma16816(float* c, uint32_t a0, uint32_t a1,
                                         uint32_t a2, uint32_t a3,
                                         uint32_t b0, uint32_t b1) {
    asm volatile(
        "mma.sync.aligned.m16n8k16.row.col.f32.f16.f16.f32 "
        "{%0,%1,%2,%3}, {%4,%5,%6,%7}, {%8,%9}, {%0,%1,%2,%3};"
        : "+f"(c[0]), "+f"(c[1]), "+f"(c[2]), "+f"(c[3])
        : "r"(a0), "r"(a1), "r"(a2), "r"(a3), "r"(b0), "r"(b1));
}
__device__ __forceinline__ void ldsm_x4(uint32_t* r, uint32_t addr) {
    asm volatile("ldmatrix.sync.aligned.m8n8.x4.shared.b16 {%0,%1,%2,%3}, [%4];"
                 : "=r"(r[0]), "=r"(r[1]), "=r"(r[2]), "=r"(r[3]) : "r"(addr));
}
// streaming adjacency load, 16B (4 ints covering one lane's full k-step need)
__device__ __forceinline__ int4 ldcs4(const int* p) {
    int4 v;
    asm volatile("ld.global.cs.v4.s32 {%0, %1, %2, %3}, [%4];"
                 : "=r"(v.x), "=r"(v.y), "=r"(v.z), "=r"(v.w) : "l"(p));
    return v;
}
// packed fp16 attention pair: src2/d2 already *L2E; mask by multiply.
// w = 2^( leaky(L2E*(src+dst)) - 4*L2E ) * mask
__device__ __forceinline__ uint32_t wpair16(uint32_t src2, uint32_t d2,
                                            int ax, int ay) {
    uint32_t e, m, l, g, w;
    asm("add.f16x2 %0, %1, %2;"    : "=r"(e) : "r"(src2), "r"(d2));
    asm("mul.f16x2 %0, %1, %2;"    : "=r"(m) : "r"(e), "r"(ALPHA2_PK));
    asm("max.f16x2 %0, %1, %2;"    : "=r"(l) : "r"(e), "r"(m));
    asm("add.f16x2 %0, %1, %2;"    : "=r"(g) : "r"(l), "r"(MESH2_PK));
    asm("ex2.approx.f16x2 %0, %0;" : "+r"(g));
    uint32_t msk = (uint32_t)ax * 0x3C00u + (uint32_t)ay * 0x3C000000u;
    asm("mul.f16x2 %0, %1, %2;"    : "=r"(w) : "r"(g), "r"(msk));
    return w;
}

// ---------------------------------------------------------------------------
// Kernel 3: HMMA masked-softmax aggregation.
// Grid 256 = 64 row-blocks x 4 j-quarters; 2 CTAs/SM. Fully-unrolled k-steps
// (ring indices are literals). NEW: j-permutation within each 16-col k-step
// group so each lane's adjacency is ONE contiguous int4 (2 LDG/step, halving
// adj L1 wavefronts) and dst is one uint2. B staging applies the matching
// even/odd half2-unit deinterleave (register component shuffle, free).
//   MMA cols (2*l4, 2*l4+1) <- j = 16ks + 4*l4 + {0,1}
//   MMA cols (2*l4+8,+9)    <- j = 16ks + 4*l4 + {2,3}
// Softmax is j-order invariant; Z (ones-B) unaffected; output cols = features.
// ---------------------------------------------------------------------------
__global__ void __launch_bounds__(256, 2) attn_kernel(const int* __restrict__ adj) {
    __shared__ __align__(1024) __half sB[2][64 * 128];   // 2 x 16 KB

    int t = threadIdx.x, lane = t & 31, w = t >> 5;
    int bx = blockIdx.x;
    int i0 = (bx >> 2) * 128, j0 = (bx & 3) * 2048;

    int l4 = lane & 3;
    int lr = lane >> 2;
    int row0 = w * 16 + lr;

    float acc[8][4];
    float zc[4];
    #pragma unroll
    for (int p = 0; p < 8; p++)
        #pragma unroll
        for (int q = 0; q < 4; q++) acc[p][q] = 0.f;
    #pragma unroll
    for (int q = 0; q < 4; q++) zc[q] = 0.f;

    // src * L2E, replicated half2
    __half2 s0h = __float2half2_rn(g_src[i0 + row0] * L2E);
    __half2 s1h = __float2half2_rn(g_src[i0 + row0 + 8] * L2E);
    uint32_t srcL0 = *(const uint32_t*)&s0h;
    uint32_t srcL1 = *(const uint32_t*)&s1h;

    // lane's adjacency base: j = j0 + 4*l4 (one int4 per k-step per row-half)
    const int* apL = adj + (size_t)(i0 + row0) * NN + j0 + l4 * 4;
    const int* apH = apL + (size_t)8 * NN;
    // lane's dst base: half2 units (j0>>1) + 2*l4 (uint2 per k-step)
    const uint32_t* dpp = g_dst16u + (j0 >> 1) + l4 * 2;

    // B-copy indices
    int fB = t >> 2, qb = (t & 3) * 4;
    const uint4* bsrc_base = (const uint4*)(g_whT16 + (size_t)fB * NN + j0);
    // ldmatrix per-lane geometry
    int fo  = (lane & 7) + ((lane & 16) >> 1);
    int cb  = (lane >> 3) & 1;
    int sw7 = lane & 7;
    uint32_t sb_base = smem_u32(sB);

    // B staging with half2-unit deinterleave per 32B group:
    //   chunk-lo gets units {0,2,4,6}, chunk-hi units {1,3,5,7}
    #define STAGE_B(dstbuf, srcptr)                                             \
        do {                                                                    \
            uint4 v0 = (srcptr)[qb], v1 = (srcptr)[qb + 1];                     \
            uint4 v2 = (srcptr)[qb + 2], v3 = (srcptr)[qb + 3];                 \
            uint4 o0 = make_uint4(v0.x, v0.z, v1.x, v1.z);                      \
            uint4 o1 = make_uint4(v0.y, v0.w, v1.y, v1.w);                      \
            uint4 o2 = make_uint4(v2.x, v2.z, v3.x, v3.z);                      \
            uint4 o3 = make_uint4(v2.y, v2.w, v3.y, v3.w);                      \
            char* db = (char*)(dstbuf) + (size_t)fB * 256;                      \
            *(uint4*)(db + (((qb + 0) ^ (fB & 7)) << 4)) = o0;                  \
            *(uint4*)(db + (((qb + 1) ^ (fB & 7)) << 4)) = o1;                  \
            *(uint4*)(db + (((qb + 2) ^ (fB & 7)) << 4)) = o2;                  \
            *(uint4*)(db + (((qb + 3) ^ (fB & 7)) << 4)) = o3;                  \
        } while (0)

    // prologue: fill B buffer 0
    STAGE_B(sB[0], bsrc_base);

    // prologue rings: adj steps 0..3, dst steps 0..1 (literal indices)
    int4 rAL[4], rAH[4];
    uint2 rD[2];
    #pragma unroll
    for (int st = 0; st < 4; st++) {
        rAL[st] = ldcs4(apL + st * 16);
        rAH[st] = ldcs4(apH + st * 16);
    }
    #pragma unroll
    for (int st = 0; st < 2; st++)
        rD[st] = *(const uint2*)(dpp + st * 8);

    const uint32_t ONES = 0x3C003C00u;  // fp16 {1,1}

    for (int lt = 0; lt < 16; lt++) {
        int s = lt & 1;
        __syncthreads();
        if (lt < 15) {   // prefetch next B tile into the other buffer
            const uint4* bs = (const uint4*)((const __half*)bsrc_base + (lt + 1) * 128);
            STAGE_B(sB[s ^ 1], bs);
        }

        uint32_t lmbase = sb_base + (uint32_t)s * 16384u + (uint32_t)fo * 256u;
        int gbase = lt * 8;

        #pragma unroll
        for (int ks = 0; ks < 8; ks++) {          // ks literal (unrolled)
            const int sa = ks & 3, sd = ks & 1;   // compile-time ring slots
            int4 aL = rAL[sa], aH = rAH[sa];
            uint2 dd = rD[sd];

            // refill slot sa with step g+4, slot sd with step g+2
            if (lt < 15 || ks < 4) {
                rAL[sa] = ldcs4(apL + (gbase + ks + 4) * 16);
                rAH[sa] = ldcs4(apH + (gbase + ks + 4) * 16);
            }
            if (lt < 15 || ks < 6)
                rD[sd] = *(const uint2*)(dpp + (gbase + ks + 2) * 8);

            // A fragment: k-lo cols use (a.x,a.y)+dd.x, k-hi cols (a.z,a.w)+dd.y
            uint32_t fa0 = wpair16(srcL0, dd.x, aL.x, aL.y);   // rows 0-7,  k-lo
            uint32_t fa1 = wpair16(srcL1, dd.x, aH.x, aH.y);   // rows 8-15, k-lo
            uint32_t fa2 = wpair16(srcL0, dd.y, aL.z, aL.w);   // rows 0-7,  k-hi
            uint32_t fa3 = wpair16(srcL1, dd.y, aH.z, aH.w);   // rows 8-15, k-hi

            uint32_t chx = (uint32_t)(((2 * ks + cb) ^ sw7) << 4);
            uint32_t b[16];
            #pragma unroll
            for (int pp = 0; pp < 4; pp++)
                ldsm_x4(b + pp * 4, lmbase + (uint32_t)(pp * 4096) + chx);

            #pragma unroll
            for (int p = 0; p < 8; p++)
                mma16816(acc[p], fa0, fa1, fa2, fa3, b[p * 2], b[p * 2 + 1]);
            mma16816(zc, fa0, fa1, fa2, fa3, ONES, ONES);
        }
    }

    // epilogue: C frags -> g_part (stride 66, aligned float2)
    size_t rbase = (size_t)bx * 128 + row0;
    #pragma unroll
    for (int p = 0; p < 8; p++) {
        float* o0 = g_part + rbase * 66 + p * 8 + l4 * 2;
        float* o1 = o0 + 8 * 66;
        *(float2*)o0 = make_float2(acc[p][0], acc[p][1]);
        *(float2*)o1 = make_float2(acc[p][2], acc[p][3]);
    }
    if (l4 == 0) {
        g_part[rbase * 66 + 64] = zc[0];
        g_part[(rbase + 8) * 66 + 64] = zc[2];
    }
}

// ---------------------------------------------------------------------------
// Kernel 4: combine 4 j-quarter partials, normalize, ELU (float2 vectorized)
// ---------------------------------------------------------------------------
__global__ __launch_bounds__(256) void combine_kernel(float* __restrict__ out) {
    int u = blockIdx.x * 256 + threadIdx.x;   // 0 .. 262143 (float2 units)
    int i = u >> 5, fp = u & 31;
    int b0 = (i >> 7) * 4, r = i & 127;
    const float* p = g_part + (size_t)(b0 * 128 + r) * 66;
    float nx = 0.f, ny = 0.f, z = 0.f;
    #pragma unroll
    for (int q = 0; q < 4; q++) {
        float2 v = *(const float2*)(p + (size_t)q * 128 * 66 + fp * 2);
        nx += v.x; ny += v.y;
        z += p[(size_t)q * 128 * 66 + 64];
    }
    float vx = nx / z, vy = ny / z;
    vx = (vx > 0.f) ? vx : expm1f(vx);
    vy = (vy > 0.f) ? vy : expm1f(vy);
    *(float2*)(out + (size_t)i * F_OUTD + fp * 2) = make_float2(vx, vy);
}

// ---------------------------------------------------------------------------
// Launch. Inputs: 0 h_nodes(8192x128 f32), 1 edge(8192 f32), 2 adj(8192^2 i32),
//                 3 weight(128x64 f32), 4 att(192 f32), 5 w_edge(64 f32)
// ---------------------------------------------------------------------------
extern "C" void kernel_launch(void* const* d_in, const int* in_sizes, int n_in,
                              void* d_out, int out_size) {
    const float* h      = (const float*)d_in[0];
    const float* edge   = (const float*)d_in[1];
    const int*   adj    = (const int*)d_in[2];
    const float* weight = (const float*)d_in[3];
    const float* att    = (const float*)d_in[4];
    const float* w_edge = (const float*)d_in[5];
    float* out = (float*)d_out;

    wh_kernel<<<NN / 32, 256>>>(h, weight);
    srcdst_kernel<<<NN / 8, 256>>>(edge, att, w_edge);
    packdst_kernel<<<NN / 512, 256>>>();
    attn_kernel<<<256, 256>>>(adj);
    combine_kernel<<<NN * F_OUTD / 512, 256>>>(out);
}